// round 2
// baseline (speedup 1.0000x reference)
#include <cuda_runtime.h>

#define L   24
#define VOL (L*L*L*L)          // 331776
#define NEVEN (VOL/2)          // 165888

struct C33 { float2 a[9]; };

__device__ __forceinline__ float2 cfma(float2 p, float2 q, float2 acc){
    acc.x = fmaf(p.x, q.x, fmaf(-p.y, q.y, acc.x));
    acc.y = fmaf(p.x, q.y, fmaf( p.y, q.x, acc.y));
    return acc;
}
// acc += p * conj(q)
__device__ __forceinline__ float2 cfma_cj(float2 p, float2 q, float2 acc){
    acc.x = fmaf(p.x, q.x, fmaf( p.y, q.y, acc.x));
    acc.y = fmaf(-p.x, q.y, fmaf( p.y, q.x, acc.y));
    return acc;
}
// acc += conj(p) * q
__device__ __forceinline__ float2 cfma_cjA(float2 p, float2 q, float2 acc){
    acc.x = fmaf(p.x, q.x, fmaf( p.y, q.y, acc.x));
    acc.y = fmaf(p.x, q.y, fmaf(-p.y, q.x, acc.y));
    return acc;
}

__device__ __forceinline__ void mzero(C33& M){
#pragma unroll
    for (int k = 0; k < 9; k++) M.a[k] = make_float2(0.f, 0.f);
}

__device__ __forceinline__ void loadM(C33& M, const float* __restrict__ re,
                                      const float* __restrict__ im, int idx){
    const float* pr = re + (long)idx * 9;
    const float* pi = im + (long)idx * 9;
#pragma unroll
    for (int k = 0; k < 9; k++) { M.a[k].x = __ldg(pr + k); M.a[k].y = __ldg(pi + k); }
}

// C = A @ B
__device__ __forceinline__ void mmul(C33& C, const C33& A, const C33& B){
#pragma unroll
    for (int r = 0; r < 3; r++)
#pragma unroll
        for (int c = 0; c < 3; c++) {
            float2 acc = make_float2(0.f, 0.f);
            acc = cfma(A.a[r*3+0], B.a[0*3+c], acc);
            acc = cfma(A.a[r*3+1], B.a[1*3+c], acc);
            acc = cfma(A.a[r*3+2], B.a[2*3+c], acc);
            C.a[r*3+c] = acc;
        }
}

// C = A @ B^dag   (C[r,c] = sum_k A[r,k] * conj(B[c,k]))
__device__ __forceinline__ void mmul_ABdag(C33& C, const C33& A, const C33& B){
#pragma unroll
    for (int r = 0; r < 3; r++)
#pragma unroll
        for (int c = 0; c < 3; c++) {
            float2 acc = make_float2(0.f, 0.f);
            acc = cfma_cj(A.a[r*3+0], B.a[c*3+0], acc);
            acc = cfma_cj(A.a[r*3+1], B.a[c*3+1], acc);
            acc = cfma_cj(A.a[r*3+2], B.a[c*3+2], acc);
            C.a[r*3+c] = acc;
        }
}

// C = A^dag @ B   (C[r,c] = sum_k conj(A[k,r]) * B[k,c])
__device__ __forceinline__ void mmul_AdagB(C33& C, const C33& A, const C33& B){
#pragma unroll
    for (int r = 0; r < 3; r++)
#pragma unroll
        for (int c = 0; c < 3; c++) {
            float2 acc = make_float2(0.f, 0.f);
            acc = cfma_cjA(A.a[0*3+r], B.a[0*3+c], acc);
            acc = cfma_cjA(A.a[1*3+r], B.a[1*3+c], acc);
            acc = cfma_cjA(A.a[2*3+r], B.a[2*3+c], acc);
            C.a[r*3+c] = acc;
        }
}

// f += cr * M   (real scalar)
__device__ __forceinline__ void axpy(C33& f, float cr, const C33& M){
#pragma unroll
    for (int k = 0; k < 9; k++) {
        f.a[k].x = fmaf(cr, M.a[k].x, f.a[k].x);
        f.a[k].y = fmaf(cr, M.a[k].y, f.a[k].y);
    }
}

__device__ __forceinline__ int SITE(int t, int z, int y, int x){
    return ((t * L + z) * L + y) * L + x;
}

// forward:  stf = X[nu][s]  @ X0[sp]  @ X[nu][s_pt]^dag
// backward: stu = X[nu][sm]^dag @ X0[sm] @ X[nu][smpt]
__device__ __forceinline__ void add_staples(
    C33& f, const float* __restrict__ re, const float* __restrict__ im,
    int nuOff, int s, int sp, int sm, int s_pt, int smpt, float cf, float cb)
{
    C33 A, B, Cm, T1, T2;
    loadM(A,  re, im, nuOff + s);     // x[nu][s]
    loadM(B,  re, im, sp);            // x0[s+nu]  (odd -> xmu_fix)
    loadM(Cm, re, im, nuOff + s_pt);  // x[nu][s+mu]
    mmul_ABdag(T1, B, Cm);
    mmul(T2, A, T1);
    axpy(f, cf, T2);

    loadM(A,  re, im, nuOff + sm);    // x[nu][s-nu]
    loadM(B,  re, im, sm);            // x0[s-nu]  (odd -> xmu_fix)
    loadM(Cm, re, im, nuOff + smpt);  // x[nu][s-nu+mu]
    mmul_AdagB(T1, A, B);
    mmul(T2, T1, Cm);
    axpy(f, cb, T2);
}

__global__ void copy_interleave(const float4* __restrict__ re,
                                const float4* __restrict__ im,
                                float4* __restrict__ out, int n4)
{
    int i = blockIdx.x * blockDim.x + threadIdx.x;
    if (i >= n4) return;
    float4 r = __ldg(re + i);
    float4 m = __ldg(im + i);
    out[2*i + 0] = make_float4(r.x, m.x, r.y, m.y);
    out[2*i + 1] = make_float4(r.z, m.z, r.w, m.w);
}

__global__ void stout_even_kernel(const float* __restrict__ xre,
                                  const float* __restrict__ xim,
                                  const float* __restrict__ coeff,
                                  float2* __restrict__ out)
{
    int tid = blockIdx.x * blockDim.x + threadIdx.x;
    if (tid >= NEVEN) return;

    int j    = tid % (L/2);
    int line = tid / (L/2);
    int y = line % L;
    int tz = line / L;
    int z = tz % L;
    int t = tz / L;
    int x = 2 * j + ((t + z + y) & 1);   // even parity: (t+z+y+x) % 2 == 0

    // scale_coeff(coeff, 0.75)/N_PLAQ = (2/pi)*0.75*atan(c)/6
    const float CS = 0.6366197723675814f * 0.75f / 6.0f;
    float c0 = CS * atanf(__ldg(coeff + 0));
    float c1 = CS * atanf(__ldg(coeff + 1));
    float c2 = CS * atanf(__ldg(coeff + 2));
    float c3 = CS * atanf(__ldg(coeff + 3));
    float c4 = CS * atanf(__ldg(coeff + 4));
    float c5 = CS * atanf(__ldg(coeff + 5));

    int tp = (t + 1 == L) ? 0 : t + 1;
    int zp = (z + 1 == L) ? 0 : z + 1;  int zm = (z == 0) ? L - 1 : z - 1;
    int yp = (y + 1 == L) ? 0 : y + 1;  int ym = (y == 0) ? L - 1 : y - 1;
    int xp = (x + 1 == L) ? 0 : x + 1;  int xm = (x == 0) ? L - 1 : x - 1;

    int s    = SITE(t,  z,  y,  x);
    int s_pt = SITE(tp, z,  y,  x);

    C33 f; mzero(f);
    // nu = 1 (Z axis)
    add_staples(f, xre, xim, 1*VOL, s, SITE(t, zp, y, x), SITE(t, zm, y, x),
                s_pt, SITE(tp, zm, y, x), c0, c1);
    // nu = 2 (Y axis)
    add_staples(f, xre, xim, 2*VOL, s, SITE(t, z, yp, x), SITE(t, z, ym, x),
                s_pt, SITE(tp, z, ym, x), c2, c3);
    // nu = 3 (X axis)
    add_staples(f, xre, xim, 3*VOL, s, SITE(t, z, y, xp), SITE(t, z, y, xm),
                s_pt, SITE(tp, z, y, xm), c4, c5);

    C33 U; loadM(U, xre, xim, s);        // xupd at even site

    // M = f @ U^dag
    C33 M; mmul_ABdag(M, f, U);

    // Z = antiherm(M) - trace/3 * I, scaled by 0.5^4
    C33 Zm;
#pragma unroll
    for (int r = 0; r < 3; r++)
#pragma unroll
        for (int c = 0; c < 3; c++) {
            float2 m1 = M.a[r*3+c];
            float2 m2 = M.a[c*3+r];          // conj
            Zm.a[r*3+c] = make_float2(0.5f * (m1.x - m2.x),
                                      0.5f * (m1.y + m2.y));
        }
    float trx = (Zm.a[0].x + Zm.a[4].x + Zm.a[8].x) * (1.f/3.f);
    float tr_y = (Zm.a[0].y + Zm.a[4].y + Zm.a[8].y) * (1.f/3.f);
    Zm.a[0].x -= trx; Zm.a[0].y -= tr_y;
    Zm.a[4].x -= trx; Zm.a[4].y -= tr_y;
    Zm.a[8].x -= trx; Zm.a[8].y -= tr_y;
#pragma unroll
    for (int k = 0; k < 9; k++) { Zm.a[k].x *= 0.0625f; Zm.a[k].y *= 0.0625f; }

    // E = I; Horner Taylor, 12 terms
    C33 E; mzero(E);
    E.a[0].x = 1.f; E.a[4].x = 1.f; E.a[8].x = 1.f;
    C33 T;
#pragma unroll
    for (int k = 12; k >= 1; k--) {
        mmul(T, Zm, E);
        float invk = 1.0f / (float)k;
#pragma unroll
        for (int q = 0; q < 9; q++) {
            E.a[q].x = T.a[q].x * invk;
            E.a[q].y = T.a[q].y * invk;
        }
        E.a[0].x += 1.f; E.a[4].x += 1.f; E.a[8].x += 1.f;
    }
    // 4 squarings
#pragma unroll
    for (int i = 0; i < 4; i++) { mmul(T, E, E); E = T; }

    // y[mu] = E @ xupd  (xmu_fix is zero at even sites)
    C33 Y; mmul(Y, E, U);

    float2* o = out + (long)s * 9;   // dir 0 region
#pragma unroll
    for (int k = 0; k < 9; k++) o[k] = Y.a[k];
}

extern "C" void kernel_launch(void* const* d_in, const int* in_sizes, int n_in,
                              void* d_out, int out_size)
{
    const float* xre   = (const float*)d_in[0];
    const float* xim   = (const float*)d_in[1];
    const float* coeff = (const float*)d_in[2];
    float* out = (float*)d_out;

    const int n4 = (4 * VOL * 9) / 4;   // 2985984 float4-groups
    copy_interleave<<<(n4 + 255) / 256, 256>>>(
        (const float4*)xre, (const float4*)xim, (float4*)out, n4);

    stout_even_kernel<<<(NEVEN + 127) / 128, 128>>>(
        xre, xim, coeff, (float2*)out);
}

// round 3
// speedup vs baseline: 1.0079x; 1.0079x over previous
#include <cuda_runtime.h>

#define L   24
#define VOL (L*L*L*L)          // 331776
#define NEVEN (VOL/2)          // 165888

struct C33 { float2 a[9]; };

__device__ __forceinline__ float2 cfma(float2 p, float2 q, float2 acc){
    acc.x = fmaf(p.x, q.x, fmaf(-p.y, q.y, acc.x));
    acc.y = fmaf(p.x, q.y, fmaf( p.y, q.x, acc.y));
    return acc;
}
// acc += p * conj(q)
__device__ __forceinline__ float2 cfma_cj(float2 p, float2 q, float2 acc){
    acc.x = fmaf(p.x, q.x, fmaf( p.y, q.y, acc.x));
    acc.y = fmaf(-p.x, q.y, fmaf( p.y, q.x, acc.y));
    return acc;
}
// acc += conj(p) * q
__device__ __forceinline__ float2 cfma_cjA(float2 p, float2 q, float2 acc){
    acc.x = fmaf(p.x, q.x, fmaf( p.y, q.y, acc.x));
    acc.y = fmaf(p.x, q.y, fmaf(-p.y, q.x, acc.y));
    return acc;
}

__device__ __forceinline__ void mzero(C33& M){
#pragma unroll
    for (int k = 0; k < 9; k++) M.a[k] = make_float2(0.f, 0.f);
}

// load complex 3x3 from interleaved float2 buffer
__device__ __forceinline__ void loadM(C33& M, const float2* __restrict__ buf, int idx){
    const float2* p = buf + (long)idx * 9;
#pragma unroll
    for (int k = 0; k < 9; k++) M.a[k] = __ldg(p + k);
}

// C = A @ B
__device__ __forceinline__ void mmul(C33& C, const C33& A, const C33& B){
#pragma unroll
    for (int r = 0; r < 3; r++)
#pragma unroll
        for (int c = 0; c < 3; c++) {
            float2 acc = make_float2(0.f, 0.f);
            acc = cfma(A.a[r*3+0], B.a[0*3+c], acc);
            acc = cfma(A.a[r*3+1], B.a[1*3+c], acc);
            acc = cfma(A.a[r*3+2], B.a[2*3+c], acc);
            C.a[r*3+c] = acc;
        }
}

// C = A @ B^dag
__device__ __forceinline__ void mmul_ABdag(C33& C, const C33& A, const C33& B){
#pragma unroll
    for (int r = 0; r < 3; r++)
#pragma unroll
        for (int c = 0; c < 3; c++) {
            float2 acc = make_float2(0.f, 0.f);
            acc = cfma_cj(A.a[r*3+0], B.a[c*3+0], acc);
            acc = cfma_cj(A.a[r*3+1], B.a[c*3+1], acc);
            acc = cfma_cj(A.a[r*3+2], B.a[c*3+2], acc);
            C.a[r*3+c] = acc;
        }
}

// C = A^dag @ B
__device__ __forceinline__ void mmul_AdagB(C33& C, const C33& A, const C33& B){
#pragma unroll
    for (int r = 0; r < 3; r++)
#pragma unroll
        for (int c = 0; c < 3; c++) {
            float2 acc = make_float2(0.f, 0.f);
            acc = cfma_cjA(A.a[0*3+r], B.a[0*3+c], acc);
            acc = cfma_cjA(A.a[1*3+r], B.a[1*3+c], acc);
            acc = cfma_cjA(A.a[2*3+r], B.a[2*3+c], acc);
            C.a[r*3+c] = acc;
        }
}

// f += cr * (A @ B)   -- fused, no full temp for the product
__device__ __forceinline__ void mmul_axpy(C33& f, float cr, const C33& A, const C33& B){
#pragma unroll
    for (int r = 0; r < 3; r++)
#pragma unroll
        for (int c = 0; c < 3; c++) {
            float2 acc = make_float2(0.f, 0.f);
            acc = cfma(A.a[r*3+0], B.a[0*3+c], acc);
            acc = cfma(A.a[r*3+1], B.a[1*3+c], acc);
            acc = cfma(A.a[r*3+2], B.a[2*3+c], acc);
            f.a[r*3+c].x = fmaf(cr, acc.x, f.a[r*3+c].x);
            f.a[r*3+c].y = fmaf(cr, acc.y, f.a[r*3+c].y);
        }
}

__device__ __forceinline__ int SITE(int t, int z, int y, int x){
    return ((t * L + z) * L + y) * L + x;
}

// forward:  f += cf * ( X[nu][s]  @ (X0[sp] @ X[nu][s_pt]^dag) )
// backward: f += cb * ( (X[nu][sm]^dag @ X0[sm]) @ X[nu][smpt] )
__device__ __forceinline__ void add_staples(
    C33& f, const float2* __restrict__ X,
    int nuOff, int s, int sp, int sm, int s_pt, int smpt, float cf, float cb)
{
    C33 A, B, Cm, T1;
    loadM(A,  X, nuOff + s);     // x[nu][s]
    loadM(B,  X, sp);            // x0[s+nu]  (odd -> xmu_fix)
    loadM(Cm, X, nuOff + s_pt);  // x[nu][s+mu]
    mmul_ABdag(T1, B, Cm);
    mmul_axpy(f, cf, A, T1);

    loadM(A,  X, nuOff + sm);    // x[nu][s-nu]
    loadM(B,  X, sm);            // x0[s-nu]  (odd -> xmu_fix)
    loadM(Cm, X, nuOff + smpt);  // x[nu][s-nu+mu]
    mmul_AdagB(T1, A, B);
    mmul_axpy(f, cb, T1, Cm);
}

__global__ void copy_interleave(const float4* __restrict__ re,
                                const float4* __restrict__ im,
                                float4* __restrict__ out, int n4)
{
    int i = blockIdx.x * blockDim.x + threadIdx.x;
    if (i >= n4) return;
    float4 r = __ldg(re + i);
    float4 m = __ldg(im + i);
    out[2*i + 0] = make_float4(r.x, m.x, r.y, m.y);
    out[2*i + 1] = make_float4(r.z, m.z, r.w, m.w);
}

__global__ void __launch_bounds__(128)
stout_even_kernel(const float* __restrict__ coeff,
                  float2* __restrict__ out)
{
    int tid = blockIdx.x * blockDim.x + threadIdx.x;
    if (tid >= NEVEN) return;

    const float2* __restrict__ X = out;   // interleaved complex image of x

    int j    = tid % (L/2);
    int line = tid / (L/2);
    int y = line % L;
    int tz = line / L;
    int z = tz % L;
    int t = tz / L;
    int x = 2 * j + ((t + z + y) & 1);   // even parity: (t+z+y+x) % 2 == 0

    // scale_coeff(coeff, 0.75)/N_PLAQ = (2/pi)*0.75*atan(c)/6
    const float CS = 0.6366197723675814f * 0.75f / 6.0f;
    float c0 = CS * atanf(__ldg(coeff + 0));
    float c1 = CS * atanf(__ldg(coeff + 1));
    float c2 = CS * atanf(__ldg(coeff + 2));
    float c3 = CS * atanf(__ldg(coeff + 3));
    float c4 = CS * atanf(__ldg(coeff + 4));
    float c5 = CS * atanf(__ldg(coeff + 5));

    int tp = (t + 1 == L) ? 0 : t + 1;
    int zp = (z + 1 == L) ? 0 : z + 1;  int zm = (z == 0) ? L - 1 : z - 1;
    int yp = (y + 1 == L) ? 0 : y + 1;  int ym = (y == 0) ? L - 1 : y - 1;
    int xp = (x + 1 == L) ? 0 : x + 1;  int xm = (x == 0) ? L - 1 : x - 1;

    int s    = SITE(t,  z,  y,  x);
    int s_pt = SITE(tp, z,  y,  x);

    C33 f; mzero(f);
    // nu = 1 (Z axis)
    add_staples(f, X, 1*VOL, s, SITE(t, zp, y, x), SITE(t, zm, y, x),
                s_pt, SITE(tp, zm, y, x), c0, c1);
    // nu = 2 (Y axis)
    add_staples(f, X, 2*VOL, s, SITE(t, z, yp, x), SITE(t, z, ym, x),
                s_pt, SITE(tp, z, ym, x), c2, c3);
    // nu = 3 (X axis)
    add_staples(f, X, 3*VOL, s, SITE(t, z, y, xp), SITE(t, z, y, xm),
                s_pt, SITE(tp, z, y, xm), c4, c5);

    C33 U; loadM(U, X, s);               // xupd at even site

    // M = f @ U^dag
    C33 M; mmul_ABdag(M, f, U);

    // Z = antiherm(M) - trace/3 * I, scaled by 0.5^4
    C33 Zm;
#pragma unroll
    for (int r = 0; r < 3; r++)
#pragma unroll
        for (int c = 0; c < 3; c++) {
            float2 m1 = M.a[r*3+c];
            float2 m2 = M.a[c*3+r];          // conj for dagger
            Zm.a[r*3+c] = make_float2(0.5f * (m1.x - m2.x),
                                      0.5f * (m1.y + m2.y));
        }
    float trx  = (Zm.a[0].x + Zm.a[4].x + Zm.a[8].x) * (1.f/3.f);
    float tr_y = (Zm.a[0].y + Zm.a[4].y + Zm.a[8].y) * (1.f/3.f);
    Zm.a[0].x -= trx; Zm.a[0].y -= tr_y;
    Zm.a[4].x -= trx; Zm.a[4].y -= tr_y;
    Zm.a[8].x -= trx; Zm.a[8].y -= tr_y;
#pragma unroll
    for (int k = 0; k < 9; k++) { Zm.a[k].x *= 0.0625f; Zm.a[k].y *= 0.0625f; }

    // Horner Taylor, 12 terms. First step: Z@I == Z exactly, so E = I + Z/12.
    C33 E;
#pragma unroll
    for (int q = 0; q < 9; q++) {
        E.a[q].x = Zm.a[q].x * (1.0f/12.0f);
        E.a[q].y = Zm.a[q].y * (1.0f/12.0f);
    }
    E.a[0].x += 1.f; E.a[4].x += 1.f; E.a[8].x += 1.f;
    C33 T;
#pragma unroll
    for (int k = 11; k >= 1; k--) {
        mmul(T, Zm, E);
        float invk = 1.0f / (float)k;
#pragma unroll
        for (int q = 0; q < 9; q++) {
            E.a[q].x = T.a[q].x * invk;
            E.a[q].y = T.a[q].y * invk;
        }
        E.a[0].x += 1.f; E.a[4].x += 1.f; E.a[8].x += 1.f;
    }
    // 4 squarings
#pragma unroll
    for (int i = 0; i < 4; i++) { mmul(T, E, E); E = T; }

    // y[mu] = E @ xupd  (xmu_fix is zero at even sites)
    C33 Y; mmul(Y, E, U);

    float2* o = out + (long)s * 9;   // dir 0 region
#pragma unroll
    for (int k = 0; k < 9; k++) o[k] = Y.a[k];
}

extern "C" void kernel_launch(void* const* d_in, const int* in_sizes, int n_in,
                              void* d_out, int out_size)
{
    const float* xre   = (const float*)d_in[0];
    const float* xim   = (const float*)d_in[1];
    const float* coeff = (const float*)d_in[2];
    float* out = (float*)d_out;

    const int n4 = (4 * VOL * 9) / 4;   // 2985984 float4-groups
    copy_interleave<<<(n4 + 255) / 256, 256>>>(
        (const float4*)xre, (const float4*)xim, (float4*)out, n4);

    stout_even_kernel<<<(NEVEN + 127) / 128, 128>>>(
        coeff, (float2*)out);
}